// round 2
// baseline (speedup 1.0000x reference)
#include <cuda_runtime.h>

// ---------------------------------------------------------------------------
// MiniMoE: out[t] = sum_k w[t,k] * relu( relu( x[t] @ W1[e]^T ) @ W2[e]^T )
// Strategy: group assignments by expert (padded to GEMM tile), two grouped
// fp32 GEMMs with row-gather on layer 1, deterministic combine.
// ---------------------------------------------------------------------------

namespace {
constexpr int T_TOK = 8192;
constexpr int D_DIM = 1024;
constexpr int E_EXP = 8;
constexpr int K_TOP = 2;
constexpr int A_TOT = T_TOK * K_TOP;        // 16384 assignments

constexpr int BM = 128;
constexpr int BN = 128;
constexpr int BK = 8;
constexpr int MAXROWS = A_TOT + E_EXP * BM; // 17408 (worst-case padding)
constexpr int MTILES  = MAXROWS / BM;       // 136
constexpr int NTILES  = D_DIM / BN;         // 8
}

// Scratch (device globals: allocation-free per harness rules)
__device__ int   g_count[E_EXP];
__device__ int   g_cursor[E_EXP];
__device__ int   g_pad_off[E_EXP + 1];
__device__ int   g_row_token[MAXROWS];      // grouped row -> token id
__device__ int   g_assign_row[A_TOT];       // assignment -> grouped row
__device__ float g_H[(size_t)MAXROWS * D_DIM];
__device__ float g_Y[(size_t)MAXROWS * D_DIM];

// ---------------------------------------------------------------------------
// Routing prep
// ---------------------------------------------------------------------------
__global__ void k_reset() {
    int i = threadIdx.x;
    if (i < E_EXP) { g_count[i] = 0; g_cursor[i] = 0; }
}

__global__ void k_hist(const int* __restrict__ idx) {
    int i = blockIdx.x * blockDim.x + threadIdx.x;
    if (i < A_TOT) atomicAdd(&g_count[idx[i]], 1);
}

__global__ void k_scan() {
    if (threadIdx.x == 0 && blockIdx.x == 0) {
        int off = 0;
        for (int e = 0; e < E_EXP; e++) {
            g_pad_off[e] = off;
            off += ((g_count[e] + BM - 1) / BM) * BM;   // tile-aligned segments
        }
        g_pad_off[E_EXP] = off;
    }
}

__global__ void k_fill() {
    int i = blockIdx.x * blockDim.x + threadIdx.x;
    if (i < MAXROWS) g_row_token[i] = 0;   // padding rows read token 0 (discarded)
}

__global__ void k_scatter(const int* __restrict__ idx) {
    int i = blockIdx.x * blockDim.x + threadIdx.x;
    if (i < A_TOT) {
        int e = idx[i];
        int pos = g_pad_off[e] + atomicAdd(&g_cursor[e], 1);
        g_row_token[pos] = i >> 1;          // token = i / K_TOP
        g_assign_row[i] = pos;
    }
}

// ---------------------------------------------------------------------------
// Grouped GEMM with fused ReLU.
// C[m][n] = relu( sum_d A[m][d] * W[e][n][d] )   (both operands K-contiguous)
// LAYER==1: A row gathered via g_row_token from X;   writes g_H
// LAYER==2: A = g_H (identity rows);                 writes g_Y
// ---------------------------------------------------------------------------
template <int LAYER>
__global__ __launch_bounds__(256, 2)
void k_gemm_relu(const float* __restrict__ X, const float* __restrict__ W) {
    __shared__ float As[BK][BM];
    __shared__ float Bs[BK][BN];

    const int m0 = blockIdx.x * BM;
    const int total = g_pad_off[E_EXP];
    if (m0 >= total) return;

    int e = 0;
#pragma unroll
    for (int i = 1; i <= E_EXP; i++)
        if (m0 >= g_pad_off[i]) e = i;      // largest e with pad_off[e] <= m0

    const float* Wc = W + (size_t)e * D_DIM * D_DIM;
    const int n0 = blockIdx.y * BN;

    const int tid  = threadIdx.x;           // 256 threads
    const int lrow = tid >> 1;              // 0..127: which tile row this thread loads
    const int lseg = (tid & 1) * 4;         // 0 or 4: which float4 of the BK=8 slice

    const float* aptr;
    if (LAYER == 1) {
        const int tok = g_row_token[m0 + lrow];
        aptr = X + (size_t)tok * D_DIM + lseg;
    } else {
        aptr = g_H + (size_t)(m0 + lrow) * D_DIM + lseg;
    }
    const float* bptr = Wc + (size_t)(n0 + lrow) * D_DIM + lseg;

    const int tx = tid & 15;                // output col group: cols tx + j*16
    const int ty = tid >> 4;                // output row group: rows ty + i*16

    float acc[8][8];
#pragma unroll
    for (int i = 0; i < 8; i++)
#pragma unroll
        for (int j = 0; j < 8; j++) acc[i][j] = 0.f;

    for (int k0 = 0; k0 < D_DIM; k0 += BK) {
        const float4 av = *reinterpret_cast<const float4*>(aptr + k0);
        const float4 bv = *reinterpret_cast<const float4*>(bptr + k0);
        __syncthreads();
        As[lseg + 0][lrow] = av.x;
        As[lseg + 1][lrow] = av.y;
        As[lseg + 2][lrow] = av.z;
        As[lseg + 3][lrow] = av.w;
        Bs[lseg + 0][lrow] = bv.x;
        Bs[lseg + 1][lrow] = bv.y;
        Bs[lseg + 2][lrow] = bv.z;
        Bs[lseg + 3][lrow] = bv.w;
        __syncthreads();
#pragma unroll
        for (int k = 0; k < BK; k++) {
            float a[8], b[8];
#pragma unroll
            for (int i = 0; i < 8; i++) a[i] = As[k][ty + i * 16];
#pragma unroll
            for (int j = 0; j < 8; j++) b[j] = Bs[k][tx + j * 16];
#pragma unroll
            for (int i = 0; i < 8; i++)
#pragma unroll
                for (int j = 0; j < 8; j++)
                    acc[i][j] = fmaf(a[i], b[j], acc[i][j]);
        }
    }

    float* Out = (LAYER == 1) ? g_H : g_Y;
#pragma unroll
    for (int i = 0; i < 8; i++) {
        const int r = m0 + ty + i * 16;
        float* orow = Out + (size_t)r * D_DIM + n0;
#pragma unroll
        for (int j = 0; j < 8; j++)
            orow[tx + j * 16] = fmaxf(acc[i][j], 0.f);
    }
}

// ---------------------------------------------------------------------------
// Deterministic combine: out[t] = w[t,0]*Y[row(t,0)] + w[t,1]*Y[row(t,1)]
// ---------------------------------------------------------------------------
__global__ void k_combine(const float* __restrict__ wts, float* __restrict__ out) {
    const int gid = blockIdx.x * blockDim.x + threadIdx.x;
    if (gid >= T_TOK * (D_DIM / 4)) return;
    const int t = gid / (D_DIM / 4);
    const int c = (gid % (D_DIM / 4)) * 4;

    const int   r0 = g_assign_row[2 * t];
    const int   r1 = g_assign_row[2 * t + 1];
    const float w0 = wts[2 * t];
    const float w1 = wts[2 * t + 1];

    const float4 y0 = *reinterpret_cast<const float4*>(&g_Y[(size_t)r0 * D_DIM + c]);
    const float4 y1 = *reinterpret_cast<const float4*>(&g_Y[(size_t)r1 * D_DIM + c]);
    float4 o;
    o.x = w0 * y0.x + w1 * y1.x;
    o.y = w0 * y0.y + w1 * y1.y;
    o.z = w0 * y0.z + w1 * y1.z;
    o.w = w0 * y0.w + w1 * y1.w;
    *reinterpret_cast<float4*>(out + (size_t)t * D_DIM + c) = o;
}

// ---------------------------------------------------------------------------
extern "C" void kernel_launch(void* const* d_in, const int* in_sizes, int n_in,
                              void* d_out, int out_size) {
    const float* x   = (const float*)d_in[0];   // [T, D]
    const int*   idx = (const int*)  d_in[1];   // [T*K]
    const float* wts = (const float*)d_in[2];   // [T*K]
    const float* W1  = (const float*)d_in[3];   // [E, D, D]
    const float* W2  = (const float*)d_in[4];   // [E, D, D]
    float* out = (float*)d_out;                 // [T, D]

    k_reset<<<1, 32>>>();
    k_hist<<<(A_TOT + 255) / 256, 256>>>(idx);
    k_scan<<<1, 1>>>();
    k_fill<<<(MAXROWS + 255) / 256, 256>>>();
    k_scatter<<<(A_TOT + 255) / 256, 256>>>(idx);

    dim3 ggrid(MTILES, NTILES);
    k_gemm_relu<1><<<ggrid, 256>>>(x, W1);
    k_gemm_relu<2><<<ggrid, 256>>>(nullptr, W2);

    k_combine<<<(T_TOK * D_DIM / 4 + 255) / 256, 256>>>(wts, out);
}

// round 4
// speedup vs baseline: 2.4952x; 2.4952x over previous
#include <cuda_runtime.h>
#include <cuda_fp16.h>
#include <cstdint>

// ---------------------------------------------------------------------------
// MiniMoE: grouped GEMMs via mma.sync (family-portable tensor path) with
// fp16 hi/lo split for fp32-grade accuracy.
//   out[t] = sum_k w[t,k] * relu( relu( x[t] @ W1[e]^T ) @ W2[e]^T )
// ---------------------------------------------------------------------------

namespace {
constexpr int T_TOK = 8192;
constexpr int D_DIM = 1024;
constexpr int E_EXP = 8;
constexpr int A_TOT = T_TOK * 2;            // 16384 assignments (K=2)

constexpr int BM = 128, BN = 128;
constexpr int KC = 32;                      // fp32 elems per K chunk
constexpr int NCHUNK = D_DIM / KC;          // 32
constexpr int MAXROWS = A_TOT + E_EXP * BM; // 17408
constexpr int MTILES  = MAXROWS / BM;       // 136
constexpr int NTILES  = D_DIM / BN;         // 8

constexpr int LDS_H   = 40;                 // halfs per smem row (80 B, ldmatrix conflict-free)
constexpr int TILE_B  = 128 * LDS_H * 2;    // 10240 B per operand tile
constexpr int OFF_AH  = 0;
constexpr int OFF_AL  = TILE_B;
constexpr int OFF_BH  = 2 * TILE_B;
constexpr int OFF_BL  = 3 * TILE_B;
constexpr int STAGE_B = 4 * TILE_B;         // 40960
constexpr int SMEM_BYTES = 2 * STAGE_B;     // 81920
}

// ---------------- scratch (device globals; no allocs) ----------------------
__device__ int    g_count[E_EXP];
__device__ int    g_cursor[E_EXP];
__device__ int    g_pad_off[E_EXP + 1];
__device__ int    g_row_token[MAXROWS];
__device__ int    g_assign_row[A_TOT];

__device__ __half g_Xh[(size_t)T_TOK * D_DIM];
__device__ __half g_Xl[(size_t)T_TOK * D_DIM];
__device__ __half g_W1h[(size_t)E_EXP * D_DIM * D_DIM];
__device__ __half g_W1l[(size_t)E_EXP * D_DIM * D_DIM];
__device__ __half g_W2h[(size_t)E_EXP * D_DIM * D_DIM];
__device__ __half g_W2l[(size_t)E_EXP * D_DIM * D_DIM];
__device__ __half g_Hh[(size_t)MAXROWS * D_DIM];
__device__ __half g_Hl[(size_t)MAXROWS * D_DIM];
__device__ float  g_Y [(size_t)MAXROWS * D_DIM];

// ---------------- PTX helpers ----------------------------------------------
__device__ __forceinline__ uint32_t smem_u32(const void* p) {
    uint32_t a;
    asm("{ .reg .u64 t; cvta.to.shared.u64 t, %1; cvt.u32.u64 %0, t; }" : "=r"(a) : "l"(p));
    return a;
}
__device__ __forceinline__ void cp16(uint32_t dst, const void* src) {
    asm volatile("cp.async.cg.shared.global [%0], [%1], 16;" :: "r"(dst), "l"(src));
}
#define CP_COMMIT() asm volatile("cp.async.commit_group;" ::: "memory")
#define CP_WAIT1()  asm volatile("cp.async.wait_group 1;" ::: "memory")

__device__ __forceinline__ void ldsm4(uint32_t& r0, uint32_t& r1, uint32_t& r2, uint32_t& r3,
                                      uint32_t addr) {
    asm volatile("ldmatrix.sync.aligned.m8n8.x4.shared.b16 {%0,%1,%2,%3}, [%4];"
                 : "=r"(r0), "=r"(r1), "=r"(r2), "=r"(r3) : "r"(addr));
}
__device__ __forceinline__ void mma16816(float* c, const uint32_t* a, const uint32_t* b) {
    asm volatile("mma.sync.aligned.m16n8k16.row.col.f32.f16.f16.f32 "
                 "{%0,%1,%2,%3}, {%4,%5,%6,%7}, {%8,%9}, {%0,%1,%2,%3};"
                 : "+f"(c[0]), "+f"(c[1]), "+f"(c[2]), "+f"(c[3])
                 : "r"(a[0]), "r"(a[1]), "r"(a[2]), "r"(a[3]), "r"(b[0]), "r"(b[1]));
}

// ---------------- routing prep ---------------------------------------------
__global__ void k_reset() {
    int i = threadIdx.x;
    if (i < E_EXP) { g_count[i] = 0; g_cursor[i] = 0; }
}
__global__ void k_hist(const int* __restrict__ idx) {
    int i = blockIdx.x * blockDim.x + threadIdx.x;
    if (i < A_TOT) atomicAdd(&g_count[idx[i]], 1);
}
__global__ void k_scan() {
    if (threadIdx.x == 0) {
        int off = 0;
        for (int e = 0; e < E_EXP; e++) {
            g_pad_off[e] = off;
            off += ((g_count[e] + BM - 1) / BM) * BM;
        }
        g_pad_off[E_EXP] = off;
    }
}
__global__ void k_fill() {
    int i = blockIdx.x * blockDim.x + threadIdx.x;
    if (i < MAXROWS) g_row_token[i] = 0;     // padding rows read token 0 (discarded)
}
__global__ void k_scatter(const int* __restrict__ idx) {
    int i = blockIdx.x * blockDim.x + threadIdx.x;
    if (i < A_TOT) {
        int e = idx[i];
        int pos = g_pad_off[e] + atomicAdd(&g_cursor[e], 1);
        g_row_token[pos] = i >> 1;
        g_assign_row[i] = pos;
    }
}

// ---------------- fp32 -> fp16 hi/lo split (bandwidth-bound) ---------------
__global__ void k_split(const float4* __restrict__ src, __half2* __restrict__ hi,
                        __half2* __restrict__ lo, int n4) {
    int i = blockIdx.x * blockDim.x + threadIdx.x;
    if (i >= n4) return;
    float4 v = src[i];
    __half2 h0 = __floats2half2_rn(v.x, v.y);
    __half2 h1 = __floats2half2_rn(v.z, v.w);
    float2 f0 = __half22float2(h0);
    float2 f1 = __half22float2(h1);
    __half2 l0 = __floats2half2_rn(v.x - f0.x, v.y - f0.y);
    __half2 l1 = __floats2half2_rn(v.z - f1.x, v.w - f1.y);
    hi[i * 2 + 0] = h0; hi[i * 2 + 1] = h1;
    lo[i * 2 + 0] = l0; lo[i * 2 + 1] = l1;
}

// ---------------------------------------------------------------------------
// Grouped split-fp16 GEMM + fused ReLU.
// C = relu(A @ W[e]^T). LAYER 1: A rows gathered from X (hi/lo), out -> Hh/Hl.
// LAYER 2: A = H rows (identity), out -> Y (fp32).
// ---------------------------------------------------------------------------
template <int LAYER>
__global__ __launch_bounds__(256, 1)
void k_gemm(const __half* __restrict__ Ah, const __half* __restrict__ Al,
            const __half* __restrict__ Bhp, const __half* __restrict__ Blp) {
    extern __shared__ __align__(128) char sm[];

    const int m0 = blockIdx.x * BM;
    if (m0 >= g_pad_off[E_EXP]) return;

    int e = 0;
#pragma unroll
    for (int i = 1; i <= E_EXP; i++)
        if (m0 >= g_pad_off[i]) e = i;

    const __half* Bh = Bhp + (size_t)e * D_DIM * D_DIM;
    const __half* Bl = Blp + (size_t)e * D_DIM * D_DIM;
    const int n0 = blockIdx.y * BN;
    const int tid = threadIdx.x;
    const uint32_t smb = smem_u32(sm);

    // ---- loader setup: thread covers rows rw and rw+64, 16B segment seg ----
    const int seg = tid & 3;
    const int rw  = tid >> 2;                 // 0..63
    const uint32_t d0 = (uint32_t)rw * 80 + seg * 16;
    const uint32_t d1 = (uint32_t)(rw + 64) * 80 + seg * 16;

    const char *pAh0, *pAh1, *pAl0, *pAl1;
    if (LAYER == 1) {
        const int t0 = g_row_token[m0 + rw];
        const int t1 = g_row_token[m0 + rw + 64];
        pAh0 = (const char*)(Ah + (size_t)t0 * D_DIM) + seg * 16;
        pAh1 = (const char*)(Ah + (size_t)t1 * D_DIM) + seg * 16;
        pAl0 = (const char*)(Al + (size_t)t0 * D_DIM) + seg * 16;
        pAl1 = (const char*)(Al + (size_t)t1 * D_DIM) + seg * 16;
    } else {
        pAh0 = (const char*)(Ah + (size_t)(m0 + rw) * D_DIM) + seg * 16;
        pAh1 = (const char*)(Ah + (size_t)(m0 + rw + 64) * D_DIM) + seg * 16;
        pAl0 = (const char*)(Al + (size_t)(m0 + rw) * D_DIM) + seg * 16;
        pAl1 = (const char*)(Al + (size_t)(m0 + rw + 64) * D_DIM) + seg * 16;
    }
    const char* pBh0 = (const char*)(Bh + (size_t)(n0 + rw) * D_DIM) + seg * 16;
    const char* pBh1 = (const char*)(Bh + (size_t)(n0 + rw + 64) * D_DIM) + seg * 16;
    const char* pBl0 = (const char*)(Bl + (size_t)(n0 + rw) * D_DIM) + seg * 16;
    const char* pBl1 = (const char*)(Bl + (size_t)(n0 + rw + 64) * D_DIM) + seg * 16;

    auto prefetch = [&](int c, int st) {
        const uint32_t b = smb + (uint32_t)st * STAGE_B;
        const size_t o = (size_t)c * 64;      // 32 halfs per chunk = 64 B
        cp16(b + OFF_AH + d0, pAh0 + o); cp16(b + OFF_AH + d1, pAh1 + o);
        cp16(b + OFF_AL + d0, pAl0 + o); cp16(b + OFF_AL + d1, pAl1 + o);
        cp16(b + OFF_BH + d0, pBh0 + o); cp16(b + OFF_BH + d1, pBh1 + o);
        cp16(b + OFF_BL + d0, pBl0 + o); cp16(b + OFF_BL + d1, pBl1 + o);
    };

    // ---- fragment addressing ----
    const int lane = tid & 31, wid = tid >> 5;
    const int wm = wid & 3;                   // M group (32 rows)
    const int wn = wid >> 2;                  // N group (64 cols)
    const uint32_t laneA = (uint32_t)(lane & 15) * 80 + (lane >> 4) * 16;
    const uint32_t laneB = (uint32_t)(((lane >> 4) & 1) * 8 + (lane & 7)) * 80
                         + ((lane >> 3) & 1) * 16;
    uint32_t aOff[2], bOff[4];
#pragma unroll
    for (int mt = 0; mt < 2; mt++) aOff[mt] = (uint32_t)(wm * 32 + mt * 16) * 80 + laneA;
#pragma unroll
    for (int tp = 0; tp < 4; tp++) bOff[tp] = (uint32_t)(wn * 64 + tp * 16) * 80 + laneB;

    float acc[16][4];
#pragma unroll
    for (int i = 0; i < 16; i++)
#pragma unroll
        for (int j = 0; j < 4; j++) acc[i][j] = 0.f;

    prefetch(0, 0); CP_COMMIT();
    prefetch(1, 1); CP_COMMIT();

    for (int c = 0; c < NCHUNK; c++) {
        CP_WAIT1();
        __syncthreads();
        const uint32_t sb = smb + (uint32_t)(c & 1) * STAGE_B;

#pragma unroll
        for (int kk = 0; kk < 2; kk++) {
            const uint32_t ko = kk * 32;      // 16 halfs
            uint32_t bf[16], ah[8], al[8];
#pragma unroll
            for (int tp = 0; tp < 4; tp++)
                ldsm4(bf[4*tp], bf[4*tp+1], bf[4*tp+2], bf[4*tp+3],
                      sb + OFF_BH + bOff[tp] + ko);
#pragma unroll
            for (int mt = 0; mt < 2; mt++)
                ldsm4(ah[4*mt], ah[4*mt+1], ah[4*mt+2], ah[4*mt+3],
                      sb + OFF_AH + aOff[mt] + ko);
#pragma unroll
            for (int mt = 0; mt < 2; mt++)
                ldsm4(al[4*mt], al[4*mt+1], al[4*mt+2], al[4*mt+3],
                      sb + OFF_AL + aOff[mt] + ko);
#pragma unroll
            for (int mt = 0; mt < 2; mt++)
#pragma unroll
                for (int nt = 0; nt < 8; nt++)
                    mma16816(acc[mt*8+nt], &ah[mt*4], &bf[nt*2]);
#pragma unroll
            for (int mt = 0; mt < 2; mt++)
#pragma unroll
                for (int nt = 0; nt < 8; nt++)
                    mma16816(acc[mt*8+nt], &al[mt*4], &bf[nt*2]);
#pragma unroll
            for (int tp = 0; tp < 4; tp++)
                ldsm4(bf[4*tp], bf[4*tp+1], bf[4*tp+2], bf[4*tp+3],
                      sb + OFF_BL + bOff[tp] + ko);
#pragma unroll
            for (int mt = 0; mt < 2; mt++)
#pragma unroll
                for (int nt = 0; nt < 8; nt++)
                    mma16816(acc[mt*8+nt], &ah[mt*4], &bf[nt*2]);
        }
        __syncthreads();
        if (c + 2 < NCHUNK) prefetch(c + 2, c & 1);
        CP_COMMIT();
    }

    // ---- epilogue: relu (+ hi/lo split for layer 1) ----
#pragma unroll
    for (int mt = 0; mt < 2; mt++) {
#pragma unroll
        for (int nt = 0; nt < 8; nt++) {
            const float* a = acc[mt*8+nt];
            const int r  = m0 + wm * 32 + mt * 16 + (lane >> 2);
            const int cc = n0 + wn * 64 + nt * 8 + (lane & 3) * 2;
            if (LAYER == 1) {
                {
                    float vx = fmaxf(a[0], 0.f), vy = fmaxf(a[1], 0.f);
                    __half2 h = __floats2half2_rn(vx, vy);
                    float2 hf = __half22float2(h);
                    __half2 l = __floats2half2_rn(vx - hf.x, vy - hf.y);
                    *reinterpret_cast<__half2*>(&g_Hh[(size_t)r * D_DIM + cc]) = h;
                    *reinterpret_cast<__half2*>(&g_Hl[(size_t)r * D_DIM + cc]) = l;
                }
                {
                    float vx = fmaxf(a[2], 0.f), vy = fmaxf(a[3], 0.f);
                    __half2 h = __floats2half2_rn(vx, vy);
                    float2 hf = __half22float2(h);
                    __half2 l = __floats2half2_rn(vx - hf.x, vy - hf.y);
                    *reinterpret_cast<__half2*>(&g_Hh[(size_t)(r + 8) * D_DIM + cc]) = h;
                    *reinterpret_cast<__half2*>(&g_Hl[(size_t)(r + 8) * D_DIM + cc]) = l;
                }
            } else {
                float2 o0 = make_float2(fmaxf(a[0], 0.f), fmaxf(a[1], 0.f));
                float2 o1 = make_float2(fmaxf(a[2], 0.f), fmaxf(a[3], 0.f));
                *reinterpret_cast<float2*>(&g_Y[(size_t)r * D_DIM + cc]) = o0;
                *reinterpret_cast<float2*>(&g_Y[(size_t)(r + 8) * D_DIM + cc]) = o1;
            }
        }
    }
}

// ---------------- deterministic combine ------------------------------------
__global__ void k_combine(const float* __restrict__ wts, float* __restrict__ out) {
    const int gid = blockIdx.x * blockDim.x + threadIdx.x;
    if (gid >= T_TOK * (D_DIM / 4)) return;
    const int t = gid / (D_DIM / 4);
    const int c = (gid % (D_DIM / 4)) * 4;

    const int   r0 = g_assign_row[2 * t];
    const int   r1 = g_assign_row[2 * t + 1];
    const float w0 = wts[2 * t];
    const float w1 = wts[2 * t + 1];

    const float4 y0 = *reinterpret_cast<const float4*>(&g_Y[(size_t)r0 * D_DIM + c]);
    const float4 y1 = *reinterpret_cast<const float4*>(&g_Y[(size_t)r1 * D_DIM + c]);
    float4 o;
    o.x = w0 * y0.x + w1 * y1.x;
    o.y = w0 * y0.y + w1 * y1.y;
    o.z = w0 * y0.z + w1 * y1.z;
    o.w = w0 * y0.w + w1 * y1.w;
    *reinterpret_cast<float4*>(out + (size_t)t * D_DIM + c) = o;
}

// ---------------------------------------------------------------------------
extern "C" void kernel_launch(void* const* d_in, const int* in_sizes, int n_in,
                              void* d_out, int out_size) {
    const float* x   = (const float*)d_in[0];
    const int*   idx = (const int*)  d_in[1];
    const float* wts = (const float*)d_in[2];
    const float* W1  = (const float*)d_in[3];
    const float* W2  = (const float*)d_in[4];
    float* out = (float*)d_out;

    cudaFuncSetAttribute(k_gemm<1>, cudaFuncAttributeMaxDynamicSharedMemorySize, SMEM_BYTES);
    cudaFuncSetAttribute(k_gemm<2>, cudaFuncAttributeMaxDynamicSharedMemorySize, SMEM_BYTES);

    k_reset<<<1, 32>>>();
    k_hist<<<(A_TOT + 255) / 256, 256>>>(idx);
    k_scan<<<1, 1>>>();
    k_fill<<<(MAXROWS + 255) / 256, 256>>>();
    k_scatter<<<(A_TOT + 255) / 256, 256>>>(idx);

    // fp32 -> fp16 hi/lo splits
    __half *xh, *xl, *w1h, *w1l, *w2h, *w2l;
    cudaGetSymbolAddress((void**)&xh,  g_Xh);
    cudaGetSymbolAddress((void**)&xl,  g_Xl);
    cudaGetSymbolAddress((void**)&w1h, g_W1h);
    cudaGetSymbolAddress((void**)&w1l, g_W1l);
    cudaGetSymbolAddress((void**)&w2h, g_W2h);
    cudaGetSymbolAddress((void**)&w2l, g_W2l);

    const int nX4 = T_TOK * D_DIM / 4;
    const int nW4 = E_EXP * D_DIM * D_DIM / 4;
    k_split<<<(nX4 + 255) / 256, 256>>>((const float4*)x,  (__half2*)xh,  (__half2*)xl,  nX4);
    k_split<<<(nW4 + 255) / 256, 256>>>((const float4*)W1, (__half2*)w1h, (__half2*)w1l, nW4);
    k_split<<<(nW4 + 255) / 256, 256>>>((const float4*)W2, (__half2*)w2h, (__half2*)w2l, nW4);

    __half *hh, *hl;
    cudaGetSymbolAddress((void**)&hh, g_Hh);
    cudaGetSymbolAddress((void**)&hl, g_Hl);

    dim3 ggrid(MTILES, NTILES);
    k_gemm<1><<<ggrid, 256, SMEM_BYTES>>>(xh, xl, w1h, w1l);
    k_gemm<2><<<ggrid, 256, SMEM_BYTES>>>(hh, hl, w2h, w2l);

    k_combine<<<(T_TOK * D_DIM / 4 + 255) / 256, 256>>>(wts, out);
}

// round 8
// speedup vs baseline: 4.0569x; 1.6259x over previous
#include <cuda_runtime.h>
#include <cuda_fp16.h>
#include <cstdint>

// ---------------------------------------------------------------------------
// MiniMoE: grouped GEMMs via mma.sync, A split into fp16 hi+lo (exact),
// B quantized to fp16 (error ~1.4e-4/layer, well under 1e-3 gate).
//   out[t] = sum_k w[t,k] * relu( relu( x[t] @ W1[e]^T ) @ W2[e]^T )
// ---------------------------------------------------------------------------

namespace {
constexpr int T_TOK = 8192;
constexpr int D_DIM = 1024;
constexpr int E_EXP = 8;
constexpr int A_TOT = T_TOK * 2;            // 16384 assignments (K=2)

constexpr int BM = 128, BN = 128;
constexpr int KC = 32;                      // fp32 elems per K chunk
constexpr int NCHUNK = D_DIM / KC;          // 32
constexpr int MAXROWS = A_TOT + E_EXP * BM; // 17408
constexpr int MTILES  = MAXROWS / BM;       // 136
constexpr int NTILES  = D_DIM / BN;         // 8

constexpr int TILE_B  = 128 * 40 * 2;       // 10240 B (80B-stride rows)
constexpr int OFF_AH  = 0;
constexpr int OFF_AL  = TILE_B;
constexpr int OFF_BH  = 2 * TILE_B;
constexpr int STAGE_B = 3 * TILE_B;         // 30720
constexpr int SMEM_BYTES = 2 * STAGE_B;     // 61440 -> 2 CTAs/SM
}

// ---------------- scratch ---------------------------------------------------
__device__ int    g_cursor[E_EXP];
__device__ int    g_pad_off[E_EXP + 1];
__device__ int    g_row_token[MAXROWS];
__device__ int    g_assign_row[A_TOT];

__device__ __half g_Xh[(size_t)T_TOK * D_DIM];
__device__ __half g_Xl[(size_t)T_TOK * D_DIM];
__device__ __half g_W1h[(size_t)E_EXP * D_DIM * D_DIM];
__device__ __half g_W2h[(size_t)E_EXP * D_DIM * D_DIM];
__device__ __half g_Hh[(size_t)MAXROWS * D_DIM];
__device__ __half g_Hl[(size_t)MAXROWS * D_DIM];
__device__ float  g_Y [(size_t)MAXROWS * D_DIM];

// ---------------- PTX helpers ----------------------------------------------
__device__ __forceinline__ uint32_t smem_u32(const void* p) {
    uint32_t a;
    asm("{ .reg .u64 t; cvta.to.shared.u64 t, %1; cvt.u32.u64 %0, t; }" : "=r"(a) : "l"(p));
    return a;
}
__device__ __forceinline__ void cp16(uint32_t dst, const void* src) {
    asm volatile("cp.async.cg.shared.global [%0], [%1], 16;" :: "r"(dst), "l"(src));
}
#define CP_COMMIT() asm volatile("cp.async.commit_group;" ::: "memory")
#define CP_WAIT1()  asm volatile("cp.async.wait_group 1;" ::: "memory")

__device__ __forceinline__ void ldsm4(uint32_t& r0, uint32_t& r1, uint32_t& r2, uint32_t& r3,
                                      uint32_t addr) {
    asm volatile("ldmatrix.sync.aligned.m8n8.x4.shared.b16 {%0,%1,%2,%3}, [%4];"
                 : "=r"(r0), "=r"(r1), "=r"(r2), "=r"(r3) : "r"(addr));
}
__device__ __forceinline__ void mma16816(float* c, const uint32_t* a, const uint32_t* b) {
    asm volatile("mma.sync.aligned.m16n8k16.row.col.f32.f16.f16.f32 "
                 "{%0,%1,%2,%3}, {%4,%5,%6,%7}, {%8,%9}, {%0,%1,%2,%3};"
                 : "+f"(c[0]), "+f"(c[1]), "+f"(c[2]), "+f"(c[3])
                 : "r"(a[0]), "r"(a[1]), "r"(a[2]), "r"(a[3]), "r"(b[0]), "r"(b[1]));
}

// ---------------- prep: hist + scan + fill (single block) -------------------
__global__ void k_prep(const int* __restrict__ idx) {
    __shared__ int cnt[E_EXP];
    const int t = threadIdx.x;
    if (t < E_EXP) cnt[t] = 0;
    __syncthreads();
    for (int i = t; i < A_TOT; i += blockDim.x) atomicAdd(&cnt[idx[i]], 1);
    __syncthreads();
    if (t == 0) {
        int off = 0;
        for (int e = 0; e < E_EXP; e++) {
            g_pad_off[e] = off;
            g_cursor[e] = 0;
            off += ((cnt[e] + BM - 1) / BM) * BM;
        }
        g_pad_off[E_EXP] = off;
    }
    for (int i = t; i < MAXROWS; i += blockDim.x) g_row_token[i] = 0;
}

__global__ void k_scatter(const int* __restrict__ idx) {
    int i = blockIdx.x * blockDim.x + threadIdx.x;
    if (i < A_TOT) {
        int e = idx[i];
        int pos = g_pad_off[e] + atomicAdd(&g_cursor[e], 1);
        g_row_token[pos] = i >> 1;
        g_assign_row[i] = pos;
    }
}

// ---------------- fused conversions: X -> hi/lo, W1/W2 -> hi ----------------
// All three regions are exactly 2^21 float4s; region = blockIdx.x >> 13.
__global__ void k_split_all(const float4* __restrict__ x,
                            const float4* __restrict__ w1,
                            const float4* __restrict__ w2) {
    const int region = blockIdx.x >> 13;
    const int i = ((blockIdx.x & 8191) << 8) + threadIdx.x;
    if (region == 0) {
        float4 v = x[i];
        __half2 h0 = __floats2half2_rn(v.x, v.y);
        __half2 h1 = __floats2half2_rn(v.z, v.w);
        float2 f0 = __half22float2(h0);
        float2 f1 = __half22float2(h1);
        reinterpret_cast<__half2*>(g_Xh)[i * 2 + 0] = h0;
        reinterpret_cast<__half2*>(g_Xh)[i * 2 + 1] = h1;
        reinterpret_cast<__half2*>(g_Xl)[i * 2 + 0] = __floats2half2_rn(v.x - f0.x, v.y - f0.y);
        reinterpret_cast<__half2*>(g_Xl)[i * 2 + 1] = __floats2half2_rn(v.z - f1.x, v.w - f1.y);
    } else {
        const float4 v = (region == 1) ? w1[i] : w2[i];
        __half* dst = (region == 1) ? g_W1h : g_W2h;
        reinterpret_cast<__half2*>(dst)[i * 2 + 0] = __floats2half2_rn(v.x, v.y);
        reinterpret_cast<__half2*>(dst)[i * 2 + 1] = __floats2half2_rn(v.z, v.w);
    }
}

// ---------------------------------------------------------------------------
// Grouped GEMM: C = relu((Ah+Al) @ Bh[e]^T), fp32 accumulate.
// LAYER 1: A rows gathered via g_row_token; out -> Hh/Hl (split).
// LAYER 2: A = H rows (identity);           out -> Y (fp32).
// ---------------------------------------------------------------------------
template <int LAYER>
__global__ __launch_bounds__(256, 2)
void k_gemm(const __half* __restrict__ Ah, const __half* __restrict__ Al,
            const __half* __restrict__ Bhp) {
    extern __shared__ __align__(128) char sm[];

    const int m0 = blockIdx.x * BM;
    if (m0 >= g_pad_off[E_EXP]) return;

    int e = 0;
#pragma unroll
    for (int i = 1; i <= E_EXP; i++)
        if (m0 >= g_pad_off[i]) e = i;

    const __half* Bh = Bhp + (size_t)e * D_DIM * D_DIM;
    const int n0 = blockIdx.y * BN;
    const int tid = threadIdx.x;
    const uint32_t smb = smem_u32(sm);

    // ---- loaders: thread covers rows rw, rw+64; 16B segment seg ----
    const int seg = tid & 3;
    const int rw  = tid >> 2;                 // 0..63
    const uint32_t d0 = (uint32_t)rw * 80 + seg * 16;
    const uint32_t d1 = (uint32_t)(rw + 64) * 80 + seg * 16;

    const char *pAh0, *pAh1, *pAl0, *pAl1;
    if (LAYER == 1) {
        const int t0 = g_row_token[m0 + rw];
        const int t1 = g_row_token[m0 + rw + 64];
        pAh0 = (const char*)(Ah + (size_t)t0 * D_DIM) + seg * 16;
        pAh1 = (const char*)(Ah + (size_t)t1 * D_DIM) + seg * 16;
        pAl0 = (const char*)(Al + (size_t)t0 * D_DIM) + seg * 16;
        pAl1 = (const char*)(Al + (size_t)t1 * D_DIM) + seg * 16;
    } else {
        pAh0 = (const char*)(Ah + (size_t)(m0 + rw) * D_DIM) + seg * 16;
        pAh1 = (const char*)(Ah + (size_t)(m0 + rw + 64) * D_DIM) + seg * 16;
        pAl0 = (const char*)(Al + (size_t)(m0 + rw) * D_DIM) + seg * 16;
        pAl1 = (const char*)(Al + (size_t)(m0 + rw + 64) * D_DIM) + seg * 16;
    }
    const char* pBh0 = (const char*)(Bh + (size_t)(n0 + rw) * D_DIM) + seg * 16;
    const char* pBh1 = (const char*)(Bh + (size_t)(n0 + rw + 64) * D_DIM) + seg * 16;

    auto prefetch = [&](int c, int st) {
        const uint32_t b = smb + (uint32_t)st * STAGE_B;
        const size_t o = (size_t)c * 64;      // 32 halfs per chunk = 64 B
        cp16(b + OFF_AH + d0, pAh0 + o); cp16(b + OFF_AH + d1, pAh1 + o);
        cp16(b + OFF_AL + d0, pAl0 + o); cp16(b + OFF_AL + d1, pAl1 + o);
        cp16(b + OFF_BH + d0, pBh0 + o); cp16(b + OFF_BH + d1, pBh1 + o);
    };

    // ---- fragment addressing (identical to R4 layout, validated) ----
    const int lane = tid & 31, wid = tid >> 5;
    const int wm = wid & 3;                   // M group (32 rows)
    const int wn = wid >> 2;                  // N group (64 cols)
    const uint32_t laneA = (uint32_t)(lane & 15) * 80 + (lane >> 4) * 16;
    const uint32_t laneB = (uint32_t)(((lane >> 4) & 1) * 8 + (lane & 7)) * 80
                         + ((lane >> 3) & 1) * 16;
    uint32_t aOff[2], bOff[4];
#pragma unroll
    for (int mt = 0; mt < 2; mt++) aOff[mt] = (uint32_t)(wm * 32 + mt * 16) * 80 + laneA;
#pragma unroll
    for (int tp = 0; tp < 4; tp++) bOff[tp] = (uint32_t)(wn * 64 + tp * 16) * 80 + laneB;

    float acc[16][4];
#pragma unroll
    for (int i = 0; i < 16; i++)
#pragma unroll
        for (int j = 0; j < 4; j++) acc[i][j] = 0.f;

    prefetch(0, 0); CP_COMMIT();
    prefetch(1, 1); CP_COMMIT();

    for (int c = 0; c < NCHUNK; c++) {
        CP_WAIT1();
        __syncthreads();
        const uint32_t sb = smb + (uint32_t)(c & 1) * STAGE_B;

#pragma unroll
        for (int kk = 0; kk < 2; kk++) {
            const uint32_t ko = kk * 32;      // 16 halfs
            uint32_t ah[8], al[8];
#pragma unroll
            for (int mt = 0; mt < 2; mt++)
                ldsm4(ah[4*mt], ah[4*mt+1], ah[4*mt+2], ah[4*mt+3],
                      sb + OFF_AH + aOff[mt] + ko);
#pragma unroll
            for (int mt = 0; mt < 2; mt++)
                ldsm4(al[4*mt], al[4*mt+1], al[4*mt+2], al[4*mt+3],
                      sb + OFF_AL + aOff[mt] + ko);
            // B consumed in 2-tile groups to cap register pressure (2 CTAs/SM)
#pragma unroll
            for (int g = 0; g < 2; g++) {
                uint32_t bf[8];
#pragma unroll
                for (int tp = 0; tp < 2; tp++)
                    ldsm4(bf[4*tp], bf[4*tp+1], bf[4*tp+2], bf[4*tp+3],
                          sb + OFF_BH + bOff[g*2+tp] + ko);
#pragma unroll
                for (int mt = 0; mt < 2; mt++)
#pragma unroll
                    for (int nt = 0; nt < 4; nt++)
                        mma16816(acc[mt*8 + g*4 + nt], &ah[mt*4], &bf[nt*2]);
#pragma unroll
                for (int mt = 0; mt < 2; mt++)
#pragma unroll
                    for (int nt = 0; nt < 4; nt++)
                        mma16816(acc[mt*8 + g*4 + nt], &al[mt*4], &bf[nt*2]);
            }
        }
        __syncthreads();
        if (c + 2 < NCHUNK) prefetch(c + 2, c & 1);
        CP_COMMIT();
    }

    // ---- epilogue ----
#pragma unroll
    for (int mt = 0; mt < 2; mt++) {
#pragma unroll
        for (int nt = 0; nt < 8; nt++) {
            const float* a = acc[mt*8+nt];
            const int r  = m0 + wm * 32 + mt * 16 + (lane >> 2);
            const int cc = n0 + wn * 64 + nt * 8 + (lane & 3) * 2;
            if (LAYER == 1) {
                {
                    float vx = fmaxf(a[0], 0.f), vy = fmaxf(a[1], 0.f);
                    __half2 h = __floats2half2_rn(vx, vy);
                    float2 hf = __half22float2(h);
                    *reinterpret_cast<__half2*>(&g_Hh[(size_t)r * D_DIM + cc]) = h;
                    *reinterpret_cast<__half2*>(&g_Hl[(size_t)r * D_DIM + cc]) =
                        __floats2half2_rn(vx - hf.x, vy - hf.y);
                }
                {
                    float vx = fmaxf(a[2], 0.f), vy = fmaxf(a[3], 0.f);
                    __half2 h = __floats2half2_rn(vx, vy);
                    float2 hf = __half22float2(h);
                    *reinterpret_cast<__half2*>(&g_Hh[(size_t)(r + 8) * D_DIM + cc]) = h;
                    *reinterpret_cast<__half2*>(&g_Hl[(size_t)(r + 8) * D_DIM + cc]) =
                        __floats2half2_rn(vx - hf.x, vy - hf.y);
                }
            } else {
                float2 o0 = make_float2(fmaxf(a[0], 0.f), fmaxf(a[1], 0.f));
                float2 o1 = make_float2(fmaxf(a[2], 0.f), fmaxf(a[3], 0.f));
                *reinterpret_cast<float2*>(&g_Y[(size_t)r * D_DIM + cc]) = o0;
                *reinterpret_cast<float2*>(&g_Y[(size_t)(r + 8) * D_DIM + cc]) = o1;
            }
        }
    }
}

// ---------------- deterministic combine ------------------------------------
__global__ void k_combine(const float* __restrict__ wts, float* __restrict__ out) {
    const int gid = blockIdx.x * blockDim.x + threadIdx.x;
    if (gid >= T_TOK * (D_DIM / 4)) return;
    const int t = gid / (D_DIM / 4);
    const int c = (gid % (D_DIM / 4)) * 4;

    const int   r0 = g_assign_row[2 * t];
    const int   r1 = g_assign_row[2 * t + 1];
    const float w0 = wts[2 * t];
    const float w1 = wts[2 * t + 1];

    const float4 y0 = *reinterpret_cast<const float4*>(&g_Y[(size_t)r0 * D_DIM + c]);
    const float4 y1 = *reinterpret_cast<const float4*>(&g_Y[(size_t)r1 * D_DIM + c]);
    float4 o;
    o.x = w0 * y0.x + w1 * y1.x;
    o.y = w0 * y0.y + w1 * y1.y;
    o.z = w0 * y0.z + w1 * y1.z;
    o.w = w0 * y0.w + w1 * y1.w;
    *reinterpret_cast<float4*>(out + (size_t)t * D_DIM + c) = o;
}

// ---------------------------------------------------------------------------
extern "C" void kernel_launch(void* const* d_in, const int* in_sizes, int n_in,
                              void* d_out, int out_size) {
    const float* x   = (const float*)d_in[0];
    const int*   idx = (const int*)  d_in[1];
    const float* wts = (const float*)d_in[2];
    const float* W1  = (const float*)d_in[3];
    const float* W2  = (const float*)d_in[4];
    float* out = (float*)d_out;

    cudaFuncSetAttribute(k_gemm<1>, cudaFuncAttributeMaxDynamicSharedMemorySize, SMEM_BYTES);
    cudaFuncSetAttribute(k_gemm<2>, cudaFuncAttributeMaxDynamicSharedMemorySize, SMEM_BYTES);

    __half *xh, *xl, *w1h, *w2h, *hh, *hl;
    cudaGetSymbolAddress((void**)&xh,  g_Xh);
    cudaGetSymbolAddress((void**)&xl,  g_Xl);
    cudaGetSymbolAddress((void**)&w1h, g_W1h);
    cudaGetSymbolAddress((void**)&w2h, g_W2h);
    cudaGetSymbolAddress((void**)&hh,  g_Hh);
    cudaGetSymbolAddress((void**)&hl,  g_Hl);

    k_prep<<<1, 1024>>>(idx);                                   // 1
    k_scatter<<<(A_TOT + 255) / 256, 256>>>(idx);               // 2
    k_split_all<<<3 * 8192, 256>>>((const float4*)x,            // 3
                                   (const float4*)W1, (const float4*)W2);

    dim3 ggrid(MTILES, NTILES);
    k_gemm<1><<<ggrid, 256, SMEM_BYTES>>>(xh, xl, w1h);         // 4 (profiled slot)
    k_gemm<2><<<ggrid, 256, SMEM_BYTES>>>(hh, hl, w2h);         // 5

    k_combine<<<(T_TOK * D_DIM / 4 + 255) / 256, 256>>>(wts, out); // 6
}

// round 9
// speedup vs baseline: 6.7393x; 1.6612x over previous
#include <cuda_runtime.h>
#include <cuda_fp16.h>
#include <cstdint>

// ---------------------------------------------------------------------------
// MiniMoE: grouped single-pass fp16 mma.sync GEMMs, fp32 accumulate.
//   out[t] = sum_k w[t,k] * relu( relu( x[t] @ W1[e]^T ) @ W2[e]^T )
// Error budget: X/W1/H/W2 fp16 quantization, ~1.4e-4 RMS each, ~3.8e-4 total.
// ---------------------------------------------------------------------------

namespace {
constexpr int T_TOK = 8192;
constexpr int D_DIM = 1024;
constexpr int E_EXP = 8;
constexpr int A_TOT = T_TOK * 2;            // 16384 assignments (K=2)

constexpr int BM = 128, BN = 128;
constexpr int KC = 32;                      // elems per K chunk
constexpr int NCHUNK = D_DIM / KC;          // 32
constexpr int MAXROWS = A_TOT + E_EXP * BM; // 17408
constexpr int MTILES  = MAXROWS / BM;       // 136
constexpr int NTILES  = D_DIM / BN;         // 8

constexpr int TILE_B  = 128 * 40 * 2;       // 10240 B (80B-stride rows)
constexpr int OFF_A   = 0;
constexpr int OFF_B   = TILE_B;
constexpr int STAGE_B = 2 * TILE_B;         // 20480
constexpr int NSTAGE  = 4;
constexpr int SMEM_BYTES = NSTAGE * STAGE_B; // 81920 -> 2 CTAs/SM
}

// ---------------- scratch ---------------------------------------------------
__device__ int    g_cursor[E_EXP];
__device__ int    g_pad_off[E_EXP + 1];
__device__ int    g_row_token[MAXROWS];
__device__ int    g_assign_row[A_TOT];

__device__ __half g_Xh[(size_t)T_TOK * D_DIM];
__device__ __half g_W1h[(size_t)E_EXP * D_DIM * D_DIM];
__device__ __half g_W2h[(size_t)E_EXP * D_DIM * D_DIM];
__device__ __half g_Hh[(size_t)MAXROWS * D_DIM];
__device__ float  g_Y [(size_t)MAXROWS * D_DIM];

// ---------------- PTX helpers ----------------------------------------------
__device__ __forceinline__ uint32_t smem_u32(const void* p) {
    uint32_t a;
    asm("{ .reg .u64 t; cvta.to.shared.u64 t, %1; cvt.u32.u64 %0, t; }" : "=r"(a) : "l"(p));
    return a;
}
__device__ __forceinline__ void cp16(uint32_t dst, const void* src) {
    asm volatile("cp.async.cg.shared.global [%0], [%1], 16;" :: "r"(dst), "l"(src));
}
#define CP_COMMIT() asm volatile("cp.async.commit_group;" ::: "memory")
#define CP_WAIT1()  asm volatile("cp.async.wait_group 1;" ::: "memory")

__device__ __forceinline__ void ldsm4(uint32_t& r0, uint32_t& r1, uint32_t& r2, uint32_t& r3,
                                      uint32_t addr) {
    asm volatile("ldmatrix.sync.aligned.m8n8.x4.shared.b16 {%0,%1,%2,%3}, [%4];"
                 : "=r"(r0), "=r"(r1), "=r"(r2), "=r"(r3) : "r"(addr));
}
__device__ __forceinline__ void mma16816(float* c, const uint32_t* a, const uint32_t* b) {
    asm volatile("mma.sync.aligned.m16n8k16.row.col.f32.f16.f16.f32 "
                 "{%0,%1,%2,%3}, {%4,%5,%6,%7}, {%8,%9}, {%0,%1,%2,%3};"
                 : "+f"(c[0]), "+f"(c[1]), "+f"(c[2]), "+f"(c[3])
                 : "r"(a[0]), "r"(a[1]), "r"(a[2]), "r"(a[3]), "r"(b[0]), "r"(b[1]));
}

// ---------------- prep: hist + scan + fill (single block) -------------------
__global__ void k_prep(const int* __restrict__ idx) {
    __shared__ int cnt[E_EXP];
    const int t = threadIdx.x;
    if (t < E_EXP) cnt[t] = 0;
    __syncthreads();
    for (int i = t; i < A_TOT; i += blockDim.x) atomicAdd(&cnt[idx[i]], 1);
    __syncthreads();
    if (t == 0) {
        int off = 0;
        for (int e = 0; e < E_EXP; e++) {
            g_pad_off[e] = off;
            g_cursor[e] = 0;
            off += ((cnt[e] + BM - 1) / BM) * BM;
        }
        g_pad_off[E_EXP] = off;
    }
    for (int i = t; i < MAXROWS; i += blockDim.x) g_row_token[i] = 0;
}

__global__ void k_scatter(const int* __restrict__ idx) {
    int i = blockIdx.x * blockDim.x + threadIdx.x;
    if (i < A_TOT) {
        int e = idx[i];
        int pos = g_pad_off[e] + atomicAdd(&g_cursor[e], 1);
        g_row_token[pos] = i >> 1;
        g_assign_row[i] = pos;
    }
}

// ---------------- fp32 -> fp16 converts (X, W1, W2) -------------------------
// All three regions are exactly 2^21 float4s; region = blockIdx.x >> 13.
__global__ void k_cvt_all(const float4* __restrict__ x,
                          const float4* __restrict__ w1,
                          const float4* __restrict__ w2) {
    const int region = blockIdx.x >> 13;
    const int i = ((blockIdx.x & 8191) << 8) + threadIdx.x;
    const float4 v = (region == 0) ? x[i] : (region == 1) ? w1[i] : w2[i];
    __half* dst = (region == 0) ? g_Xh : (region == 1) ? g_W1h : g_W2h;
    reinterpret_cast<__half2*>(dst)[i * 2 + 0] = __floats2half2_rn(v.x, v.y);
    reinterpret_cast<__half2*>(dst)[i * 2 + 1] = __floats2half2_rn(v.z, v.w);
}

// ---------------------------------------------------------------------------
// Grouped GEMM: C = relu(A @ B[e]^T), fp16 operands, fp32 accumulate.
// LAYER 1: A rows gathered via g_row_token; out -> Hh (fp16).
// LAYER 2: A = H rows (identity);           out -> Y (fp32).
// 4-stage cp.async ring, prefetch distance 2, ONE barrier per chunk.
// ---------------------------------------------------------------------------
template <int LAYER>
__global__ __launch_bounds__(256, 2)
void k_gemm(const __half* __restrict__ Ap, const __half* __restrict__ Bp) {
    extern __shared__ __align__(128) char sm[];

    const int m0 = blockIdx.x * BM;
    if (m0 >= g_pad_off[E_EXP]) return;

    int e = 0;
#pragma unroll
    for (int i = 1; i <= E_EXP; i++)
        if (m0 >= g_pad_off[i]) e = i;

    const __half* Bh = Bp + (size_t)e * D_DIM * D_DIM;
    const int n0 = blockIdx.y * BN;
    const int tid = threadIdx.x;
    const uint32_t smb = smem_u32(sm);

    // ---- loaders: thread covers rows rw, rw+64; 16B segment seg ----
    const int seg = tid & 3;
    const int rw  = tid >> 2;                 // 0..63
    const uint32_t d0 = (uint32_t)rw * 80 + seg * 16;
    const uint32_t d1 = (uint32_t)(rw + 64) * 80 + seg * 16;

    const char *pA0, *pA1;
    if (LAYER == 1) {
        const int t0 = g_row_token[m0 + rw];
        const int t1 = g_row_token[m0 + rw + 64];
        pA0 = (const char*)(Ap + (size_t)t0 * D_DIM) + seg * 16;
        pA1 = (const char*)(Ap + (size_t)t1 * D_DIM) + seg * 16;
    } else {
        pA0 = (const char*)(Ap + (size_t)(m0 + rw) * D_DIM) + seg * 16;
        pA1 = (const char*)(Ap + (size_t)(m0 + rw + 64) * D_DIM) + seg * 16;
    }
    const char* pB0 = (const char*)(Bh + (size_t)(n0 + rw) * D_DIM) + seg * 16;
    const char* pB1 = (const char*)(Bh + (size_t)(n0 + rw + 64) * D_DIM) + seg * 16;

    auto prefetch = [&](int c, int st) {
        const uint32_t b = smb + (uint32_t)st * STAGE_B;
        const size_t o = (size_t)c * 64;      // 32 halfs per chunk = 64 B
        cp16(b + OFF_A + d0, pA0 + o); cp16(b + OFF_A + d1, pA1 + o);
        cp16(b + OFF_B + d0, pB0 + o); cp16(b + OFF_B + d1, pB1 + o);
    };

    // ---- fragment addressing (validated layout) ----
    const int lane = tid & 31, wid = tid >> 5;
    const int wm = wid & 3;                   // M group (32 rows)
    const int wn = wid >> 2;                  // N group (64 cols)
    const uint32_t laneA = (uint32_t)(lane & 15) * 80 + (lane >> 4) * 16;
    const uint32_t laneB = (uint32_t)(((lane >> 4) & 1) * 8 + (lane & 7)) * 80
                         + ((lane >> 3) & 1) * 16;
    uint32_t aOff[2], bOff[4];
#pragma unroll
    for (int mt = 0; mt < 2; mt++) aOff[mt] = (uint32_t)(wm * 32 + mt * 16) * 80 + laneA;
#pragma unroll
    for (int tp = 0; tp < 4; tp++) bOff[tp] = (uint32_t)(wn * 64 + tp * 16) * 80 + laneB;

    float acc[16][4];
#pragma unroll
    for (int i = 0; i < 16; i++)
#pragma unroll
        for (int j = 0; j < 4; j++) acc[i][j] = 0.f;

    prefetch(0, 0); CP_COMMIT();
    prefetch(1, 1); CP_COMMIT();

    for (int c = 0; c < NCHUNK; c++) {
        CP_WAIT1();                           // stage c complete (c+1 may be in flight)
        __syncthreads();                      // all warps done reading stage (c+2)&3's slot
        if (c + 2 < NCHUNK) prefetch(c + 2, (c + 2) & 3);
        CP_COMMIT();

        const uint32_t sb = smb + (uint32_t)(c & 3) * STAGE_B;
#pragma unroll
        for (int kk = 0; kk < 2; kk++) {
            const uint32_t ko = kk * 32;      // 16 halfs
            uint32_t ah[8];
#pragma unroll
            for (int mt = 0; mt < 2; mt++)
                ldsm4(ah[4*mt], ah[4*mt+1], ah[4*mt+2], ah[4*mt+3],
                      sb + OFF_A + aOff[mt] + ko);
#pragma unroll
            for (int g = 0; g < 2; g++) {
                uint32_t bf[8];
#pragma unroll
                for (int tp = 0; tp < 2; tp++)
                    ldsm4(bf[4*tp], bf[4*tp+1], bf[4*tp+2], bf[4*tp+3],
                          sb + OFF_B + bOff[g*2+tp] + ko);
#pragma unroll
                for (int mt = 0; mt < 2; mt++)
#pragma unroll
                    for (int nt = 0; nt < 4; nt++)
                        mma16816(acc[mt*8 + g*4 + nt], &ah[mt*4], &bf[nt*2]);
            }
        }
    }

    // ---- epilogue ----
#pragma unroll
    for (int mt = 0; mt < 2; mt++) {
#pragma unroll
        for (int nt = 0; nt < 8; nt++) {
            const float* a = acc[mt*8+nt];
            const int r  = m0 + wm * 32 + mt * 16 + (lane >> 2);
            const int cc = n0 + wn * 64 + nt * 8 + (lane & 3) * 2;
            if (LAYER == 1) {
                *reinterpret_cast<__half2*>(&g_Hh[(size_t)r * D_DIM + cc]) =
                    __floats2half2_rn(fmaxf(a[0], 0.f), fmaxf(a[1], 0.f));
                *reinterpret_cast<__half2*>(&g_Hh[(size_t)(r + 8) * D_DIM + cc]) =
                    __floats2half2_rn(fmaxf(a[2], 0.f), fmaxf(a[3], 0.f));
            } else {
                float2 o0 = make_float2(fmaxf(a[0], 0.f), fmaxf(a[1], 0.f));
                float2 o1 = make_float2(fmaxf(a[2], 0.f), fmaxf(a[3], 0.f));
                *reinterpret_cast<float2*>(&g_Y[(size_t)r * D_DIM + cc]) = o0;
                *reinterpret_cast<float2*>(&g_Y[(size_t)(r + 8) * D_DIM + cc]) = o1;
            }
        }
    }
}

// ---------------- deterministic combine ------------------------------------
__global__ void k_combine(const float* __restrict__ wts, float* __restrict__ out) {
    const int gid = blockIdx.x * blockDim.x + threadIdx.x;
    if (gid >= T_TOK * (D_DIM / 4)) return;
    const int t = gid / (D_DIM / 4);
    const int c = (gid % (D_DIM / 4)) * 4;

    const int   r0 = g_assign_row[2 * t];
    const int   r1 = g_assign_row[2 * t + 1];
    const float w0 = wts[2 * t];
    const float w1 = wts[2 * t + 1];

    const float4 y0 = *reinterpret_cast<const float4*>(&g_Y[(size_t)r0 * D_DIM + c]);
    const float4 y1 = *reinterpret_cast<const float4*>(&g_Y[(size_t)r1 * D_DIM + c]);
    float4 o;
    o.x = w0 * y0.x + w1 * y1.x;
    o.y = w0 * y0.y + w1 * y1.y;
    o.z = w0 * y0.z + w1 * y1.z;
    o.w = w0 * y0.w + w1 * y1.w;
    *reinterpret_cast<float4*>(out + (size_t)t * D_DIM + c) = o;
}

// ---------------------------------------------------------------------------
extern "C" void kernel_launch(void* const* d_in, const int* in_sizes, int n_in,
                              void* d_out, int out_size) {
    const float* x   = (const float*)d_in[0];
    const int*   idx = (const int*)  d_in[1];
    const float* wts = (const float*)d_in[2];
    const float* W1  = (const float*)d_in[3];
    const float* W2  = (const float*)d_in[4];
    float* out = (float*)d_out;

    cudaFuncSetAttribute(k_gemm<1>, cudaFuncAttributeMaxDynamicSharedMemorySize, SMEM_BYTES);
    cudaFuncSetAttribute(k_gemm<2>, cudaFuncAttributeMaxDynamicSharedMemorySize, SMEM_BYTES);

    __half *xh, *w1h, *w2h, *hh;
    cudaGetSymbolAddress((void**)&xh,  g_Xh);
    cudaGetSymbolAddress((void**)&w1h, g_W1h);
    cudaGetSymbolAddress((void**)&w2h, g_W2h);
    cudaGetSymbolAddress((void**)&hh,  g_Hh);

    k_prep<<<1, 1024>>>(idx);                                   // 1
    k_scatter<<<(A_TOT + 255) / 256, 256>>>(idx);               // 2
    k_cvt_all<<<3 * 8192, 256>>>((const float4*)x,              // 3
                                 (const float4*)W1, (const float4*)W2);

    dim3 ggrid(MTILES, NTILES);
    k_gemm<1><<<ggrid, 256, SMEM_BYTES>>>(xh, w1h);             // 4 (profiled slot)
    k_gemm<2><<<ggrid, 256, SMEM_BYTES>>>(hh, w2h);             // 5

    k_combine<<<(T_TOK * D_DIM / 4 + 255) / 256, 256>>>(wts, out); // 6
}